// round 14
// baseline (speedup 1.0000x reference)
#include <cuda_runtime.h>
#include <cuda_fp16.h>
#include <cstdint>

// Problem constants
#define IM_PIX   16384      // 128*128 pixels
#define BC       32         // 2*16 maps
#define HT_BINS  33120      // 184*180
#define HB2      (HT_BINS / 2)   // 16560, bin-split point
#define N_VOTES  4000000
#define INV_NORM (1.0f/128.0f)
#define NREP     8          // bucket segments per bin
#define RCAP     32         // capacity per segment; Pois(15.1) + exact fallback
#define CAPTOT   (NREP * RCAP)   // 256

// Scratch (__device__ globals; allocation-free rule). Zero-initialized at load;
// accum paths re-zero their bins' g_cnt/g_acc every call (deterministic).
__device__ __half   g_xTh[IM_PIX * BC];                 // pixel-major fp16 table, 1 MB
__device__ float    g_acc[HT_BINS * BC];                // overflow-fallback accumulator
__device__ int      g_cnt[HT_BINS * NREP];              // per-segment counters
__device__ unsigned g_bucket[(size_t)HT_BINS * CAPTOT]; // packed votes p<<16|fp16(w)

#define TRANS_BLOCKS 256                    // IM_PIX/64 transpose tiles
#define SCAT_THREADS (N_VOTES / 8)          // 500,000 threads, 8 votes each
#define SCAT_BLOCKS  2070                   // 2070*256 = 529,920 >= SCAT_THREADS
#define ACC_BLOCKS_H (HB2 / 4)              // 4140 accum blocks per half

// ---------------------------------------------------------------------------
// Transpose tile: x [BC, IM_PIX] fp32 -> g_xTh [IM_PIX, BC] fp16
// ---------------------------------------------------------------------------
__device__ __forceinline__ void transpose_tile(const float* __restrict__ x, int blk) {
    __shared__ float tile[32][64 + 1];
    int p0 = blk * 64;
    int t  = threadIdx.x;
    #pragma unroll
    for (int i = 0; i < 8; i++) {
        int idx = t + i * 256;          // idx = m*64 + pl
        int m  = idx >> 6;
        int pl = idx & 63;
        tile[m][pl] = x[(size_t)m * IM_PIX + p0 + pl];
    }
    __syncthreads();
    #pragma unroll
    for (int i = 0; i < 8; i++) {
        int idx = t + i * 256;          // idx = pl*32 + m
        int pl = idx >> 5;
        int m  = idx & 31;
        g_xTh[(size_t)(p0 + pl) * BC + m] = __float2half(tile[m][pl]);
    }
}

// ---------------------------------------------------------------------------
// Scatter 8 votes/thread into per-bin segment buckets, restricted to bins in
// [lo, hi). Other votes are skipped (they belong to the other pass).
// Overflow fallback (prob ~0): exact atomics from original x.
// ---------------------------------------------------------------------------
__device__ __forceinline__ void scatter_range(const float* __restrict__ x,
                                              const int*   __restrict__ vp,
                                              const int*   __restrict__ vb,
                                              const float* __restrict__ vw,
                                              int blk, int lo, int hi) {
    int t = blk * 256 + threadIdx.x;
    if (t >= SCAT_THREADS) return;

    int4   pa = __ldcs(reinterpret_cast<const int4*>(vp) + 2 * t);
    int4   pb = __ldcs(reinterpret_cast<const int4*>(vp) + 2 * t + 1);
    int4   ba = __ldcs(reinterpret_cast<const int4*>(vb) + 2 * t);
    int4   bb = __ldcs(reinterpret_cast<const int4*>(vb) + 2 * t + 1);
    float4 wa = __ldcs(reinterpret_cast<const float4*>(vw) + 2 * t);
    float4 wb = __ldcs(reinterpret_cast<const float4*>(vw) + 2 * t + 1);

    int   ps[8] = {pa.x, pa.y, pa.z, pa.w, pb.x, pb.y, pb.z, pb.w};
    int   bs[8] = {ba.x, ba.y, ba.z, ba.w, bb.x, bb.y, bb.z, bb.w};
    float ws[8] = {wa.x, wa.y, wa.z, wa.w, wb.x, wb.y, wb.z, wb.w};

    bool inr[8];
    int  pos[8];
    #pragma unroll
    for (int k = 0; k < 8; k++) {               // vote k -> segment k of its bin
        inr[k] = (bs[k] >= lo) && (bs[k] < hi);
        pos[k] = inr[k] ? atomicAdd(&g_cnt[bs[k] * NREP + k], 1) : 0;
    }

    #pragma unroll
    for (int k = 0; k < 8; k++) {
        if (!inr[k]) continue;
        if (pos[k] < RCAP) {
            unsigned packed = ((unsigned)ps[k] << 16)
                            | (unsigned)__half_as_ushort(__float2half(ws[k]));
            __stcs(&g_bucket[(size_t)bs[k] * CAPTOT + k * RCAP + pos[k]], packed);
        } else {                                 // ~1e-5 of votes: exact fallback
            float* dst = g_acc + (size_t)bs[k] * BC;
            #pragma unroll
            for (int m = 0; m < BC; m++)
                atomicAdd(dst + m, x[(size_t)m * IM_PIX + ps[k]] * ws[k]);
        }
    }
}

// ---------------------------------------------------------------------------
// Accumulate 4 bins (R10 structure): block = 8 warps = 4 bins x 2 warps;
// warp part p owns segments [4p, 4p+4), each exactly one 32-wide chunk.
//   - 1 uint4 LDG for 4 counters, 4 independent bucket LDGs in flight upfront
//   oct = lane>>2 : vote within step;  sub = lane&3 : map octet -> LDG.128
// Pads have pk=0 -> w=+0.0 -> harmless FMAs.
// Tail: oct-fold, smem combine, coalesced output, re-zero g_cnt/g_acc.
// ---------------------------------------------------------------------------
__device__ __forceinline__ void accum_bins(float* __restrict__ out, int b0) {
    __shared__ float s_part[4][2][32];     // [bin_local][part][map]

    int wid  = threadIdx.x >> 5;
    int lane = threadIdx.x & 31;
    int bl   = wid >> 1;
    int part = wid & 1;
    int b    = b0 + bl;
    int oct  = lane >> 2;
    int sub  = lane & 3;

    // counters for my 4 segments: one 16B load
    uint4 c4 = *reinterpret_cast<const uint4*>(g_cnt + b * NREP + part * 4);
    int n[4] = {(int)c4.x, (int)c4.y, (int)c4.z, (int)c4.w};
    #pragma unroll
    for (int rr = 0; rr < 4; rr++) if (n[rr] > RCAP) n[rr] = RCAP;

    // all 4 bucket chunks in flight before any processing
    const unsigned* segbase = g_bucket + (size_t)b * CAPTOT + part * (4 * RCAP);
    unsigned pk[4];
    #pragma unroll
    for (int rr = 0; rr < 4; rr++)
        pk[rr] = (lane < n[rr]) ? __ldg(segbase + rr * RCAP + lane) : 0u;

    float acc[8] = {0.f, 0.f, 0.f, 0.f, 0.f, 0.f, 0.f, 0.f};
    if (part == 0 && oct == 0) {           // fold (normally zero) overflow row once
        float4 a0 = *reinterpret_cast<const float4*>(g_acc + (size_t)b * BC + sub * 8);
        float4 a1 = *reinterpret_cast<const float4*>(g_acc + (size_t)b * BC + sub * 8 + 4);
        acc[0] = a0.x; acc[1] = a0.y; acc[2] = a0.z; acc[3] = a0.w;
        acc[4] = a1.x; acc[5] = a1.y; acc[6] = a1.z; acc[7] = a1.w;
    }

    const char* xbase = reinterpret_cast<const char*>(g_xTh);

    #pragma unroll
    for (int rr = 0; rr < 4; rr++) {
        #pragma unroll
        for (int s = 0; s < RCAP; s += 8) {
            if (s >= n[rr]) break;         // warp-uniform, chunk granularity
            unsigned pv = __shfl_sync(0xffffffffu, pk[rr], s + oct);
            float w = __half2float(__ushort_as_half((unsigned short)(pv & 0xffffu)));
            unsigned off = (pv >> 10) & 0xFFFFC0u;   // pixel * 64 bytes
            uint4 u = __ldg(reinterpret_cast<const uint4*>(xbase + off + sub * 16));
            float2 f0 = __half22float2(*reinterpret_cast<__half2*>(&u.x));
            float2 f1 = __half22float2(*reinterpret_cast<__half2*>(&u.y));
            float2 f2 = __half22float2(*reinterpret_cast<__half2*>(&u.z));
            float2 f3 = __half22float2(*reinterpret_cast<__half2*>(&u.w));
            acc[0] += f0.x * w;  acc[1] += f0.y * w;
            acc[2] += f1.x * w;  acc[3] += f1.y * w;
            acc[4] += f2.x * w;  acc[5] += f2.y * w;
            acc[6] += f3.x * w;  acc[7] += f3.y * w;
        }
    }

    // fold the 8 oct groups (vote selectors): xor offsets 4, 8, 16
    #pragma unroll
    for (int ofs = 4; ofs <= 16; ofs <<= 1) {
        #pragma unroll
        for (int i = 0; i < 8; i++)
            acc[i] += __shfl_xor_sync(0xffffffffu, acc[i], ofs);
    }

    if (oct == 0) {                        // lanes 0..3 hold maps [8*sub, 8*sub+8)
        #pragma unroll
        for (int i = 0; i < 8; i++)
            s_part[bl][part][sub * 8 + i] = acc[i];
    }
    __syncthreads();

    int t = threadIdx.x;
    if (t < 128) {
        // t = m*4 + bl -> 4 consecutive bins per map (16B coalesced)
        int m   = t >> 2;
        int obl = t & 3;
        float v = s_part[obl][0][m] + s_part[obl][1][m];
        out[(size_t)m * HT_BINS + b0 + obl] = v * INV_NORM;
    }
    // re-zero state for the next call (this block's bins were fully read
    // before the __syncthreads above; no other block touches them)
    if (t < 8)                             // 4 bins * 8 counters = 32 ints = 8 int4
        reinterpret_cast<int4*>(g_cnt + b0 * NREP)[t] = make_int4(0, 0, 0, 0);
    if (t >= 128 && t < 160)               // 4 bins * 32 floats = 32 float4
        reinterpret_cast<float4*>(g_acc + (size_t)b0 * BC)[t - 128] =
            make_float4(0.f, 0.f, 0.f, 0.f);
}

// ---------------------------------------------------------------------------
// K1: transpose (blocks 0..255) + scatter of LOW bins [0, HB2)
// ---------------------------------------------------------------------------
__global__ void __launch_bounds__(256) k1_kernel(const float* __restrict__ x,
                                                 const int*   __restrict__ vp,
                                                 const int*   __restrict__ vb,
                                                 const float* __restrict__ vw) {
    if (blockIdx.x < TRANS_BLOCKS)
        transpose_tile(x, blockIdx.x);
    else
        scatter_range(x, vp, vb, vw, blockIdx.x - TRANS_BLOCKS, 0, HB2);
}

// ---------------------------------------------------------------------------
// K2: heterogeneous — accum LOW bins concurrently with scatter of HIGH bins.
// Block types interleaved 2:1 so every wave co-runs both (accum: L1tex/issue;
// scatter: L2 RMW) and the phases genuinely overlap.
//   grid = 3 * 2070 = 6210;  i%3==2 -> scatter block i/3; else accum block
//   2*(i/3) + i%3  (covers [0, 4140) exactly)
// ---------------------------------------------------------------------------
__global__ void __launch_bounds__(256) k2_kernel(float* __restrict__ out,
                                                 const float* __restrict__ x,
                                                 const int*   __restrict__ vp,
                                                 const int*   __restrict__ vb,
                                                 const float* __restrict__ vw) {
    int g = blockIdx.x / 3;
    int r = blockIdx.x % 3;
    if (r == 2)
        scatter_range(x, vp, vb, vw, g, HB2, HT_BINS);
    else
        accum_bins(out, (2 * g + r) * 4);
}

// ---------------------------------------------------------------------------
// K3: accum HIGH bins [HB2, HT_BINS)
// ---------------------------------------------------------------------------
__global__ void __launch_bounds__(256) k3_kernel(float* __restrict__ out) {
    accum_bins(out, HB2 + blockIdx.x * 4);
}

// ---------------------------------------------------------------------------
// Launch pipeline: 3 kernels, all async, graph-capturable
// ---------------------------------------------------------------------------
extern "C" void kernel_launch(void* const* d_in, const int* in_sizes, int n_in,
                              void* d_out, int out_size) {
    const float* x  = (const float*)d_in[0];   // [2,16,128,128] fp32
    const int*   vp = (const int*)  d_in[1];   // vote_pixel  [4M]
    const int*   vb = (const int*)  d_in[2];   // vote_bin    [4M]
    const float* vw = (const float*)d_in[3];   // vote_weight [4M]
    float* out = (float*)d_out;                // [2,16,184,180] fp32

    k1_kernel<<<TRANS_BLOCKS + SCAT_BLOCKS, 256>>>(x, vp, vb, vw);
    k2_kernel<<<3 * SCAT_BLOCKS, 256>>>(out, x, vp, vb, vw);
    k3_kernel<<<ACC_BLOCKS_H, 256>>>(out);
}

// round 15
// speedup vs baseline: 1.0881x; 1.0881x over previous
#include <cuda_runtime.h>
#include <cuda_fp16.h>
#include <cstdint>

// Problem constants
#define IM_PIX   16384      // 128*128 pixels
#define BC       32         // 2*16 maps
#define HT_BINS  33120      // 184*180
#define N_VOTES  4000000
#define INV_NORM (1.0f/128.0f)
#define NREP     8          // bucket segments per bin
#define RCAP     32         // capacity per segment; Pois(15.1), P(>32)~3e-5 + exact fallback
#define CAPTOT   (NREP * RCAP)   // 256

// Scratch (__device__ globals; allocation-free rule). Zero-initialized at load;
// accum_kernel re-zeroes g_cnt/g_acc at the end of every call (deterministic).
__device__ __half   g_xTh[IM_PIX * BC];                 // pixel-major fp16 table, 1 MB
__device__ float    g_acc[HT_BINS * BC];                // overflow-fallback accumulator
__device__ int      g_cnt[HT_BINS * NREP];              // per-segment counters
__device__ unsigned g_bucket[(size_t)HT_BINS * CAPTOT]; // packed votes p<<16|fp16(w)

#define TRANS_BLOCKS 256                   // IM_PIX/64 transpose tiles
#define SCAT_THREADS (N_VOTES / 8)         // 500,000
#define SCAT_BLOCKS  ((SCAT_THREADS + 255) / 256)

// ---------------------------------------------------------------------------
// Fused kernel: blocks [0,256) transpose x -> g_xTh (fp16 pixel-major);
// blocks [256, ...) scatter 8 votes/thread into per-bin segment buckets.
// Transpose blocks launch first and hide under the scatter work.
// ---------------------------------------------------------------------------
__global__ void scatter_transpose_kernel(const float* __restrict__ x,
                                         const int*   __restrict__ vp,
                                         const int*   __restrict__ vb,
                                         const float* __restrict__ vw) {
    if (blockIdx.x < TRANS_BLOCKS) {
        __shared__ float tile[32][64 + 1];
        int p0 = blockIdx.x * 64;
        int t  = threadIdx.x;
        #pragma unroll
        for (int i = 0; i < 8; i++) {
            int idx = t + i * 256;          // idx = m*64 + pl
            int m  = idx >> 6;
            int pl = idx & 63;
            tile[m][pl] = x[(size_t)m * IM_PIX + p0 + pl];
        }
        __syncthreads();
        #pragma unroll
        for (int i = 0; i < 8; i++) {
            int idx = t + i * 256;          // idx = pl*32 + m
            int pl = idx >> 5;
            int m  = idx & 31;
            g_xTh[(size_t)(p0 + pl) * BC + m] = __float2half(tile[m][pl]);
        }
        return;
    }

    int t = (blockIdx.x - TRANS_BLOCKS) * blockDim.x + threadIdx.x;
    if (t >= SCAT_THREADS) return;

    int4   pa = __ldcs(reinterpret_cast<const int4*>(vp) + 2 * t);
    int4   pb = __ldcs(reinterpret_cast<const int4*>(vp) + 2 * t + 1);
    int4   ba = __ldcs(reinterpret_cast<const int4*>(vb) + 2 * t);
    int4   bb = __ldcs(reinterpret_cast<const int4*>(vb) + 2 * t + 1);
    float4 wa = __ldcs(reinterpret_cast<const float4*>(vw) + 2 * t);
    float4 wb = __ldcs(reinterpret_cast<const float4*>(vw) + 2 * t + 1);

    int   ps[8] = {pa.x, pa.y, pa.z, pa.w, pb.x, pb.y, pb.z, pb.w};
    int   bs[8] = {ba.x, ba.y, ba.z, ba.w, bb.x, bb.y, bb.z, bb.w};
    float ws[8] = {wa.x, wa.y, wa.z, wa.w, wb.x, wb.y, wb.z, wb.w};

    int pos[8];
    #pragma unroll
    for (int k = 0; k < 8; k++)                 // vote k -> segment k of its bin
        pos[k] = atomicAdd(&g_cnt[bs[k] * NREP + k], 1);

    #pragma unroll
    for (int k = 0; k < 8; k++) {
        if (pos[k] < RCAP) {
            unsigned packed = ((unsigned)ps[k] << 16)
                            | (unsigned)__half_as_ushort(__float2half(ws[k]));
            __stcs(&g_bucket[(size_t)bs[k] * CAPTOT + k * RCAP + pos[k]], packed);
        } else {                                 // ~1e-5 of votes: exact fallback
            float* dst = g_acc + (size_t)bs[k] * BC;
            #pragma unroll
            for (int m = 0; m < BC; m++)
                atomicAdd(dst + m, x[(size_t)m * IM_PIX + ps[k]] * ws[k]);
        }
    }
}

// ---------------------------------------------------------------------------
// Accumulate: block = 8 warps = 4 bins x 2 warps; warp part p owns segments
// [4p, 4p+4). Each segment is exactly one 32-wide chunk:
//   - 1 uint4 LDG for the 4 counters
//   - 4 independent bucket LDGs issued up front (MLP vs L2 latency)
//   oct = lane>>2 : which of 8 votes per step;  sub = lane&3 : map octet
//   -> one LDG.128 (8 halves) per lane per step
// Pads (lane >= n) have pk=0 -> w=+0.0 -> harmless FMAs.
// Tail: fold, smem combine, coalesced output, then RE-ZERO g_cnt/g_acc for
// the next call.
// ---------------------------------------------------------------------------
__global__ void accum_kernel(float* __restrict__ out) {
    __shared__ float s_part[4][2][32];     // [bin_local][part][map]

    int wid  = threadIdx.x >> 5;
    int lane = threadIdx.x & 31;
    int bl   = wid >> 1;
    int part = wid & 1;
    int b0   = blockIdx.x * 4;
    int b    = b0 + bl;                    // HT_BINS % 4 == 0
    int oct  = lane >> 2;
    int sub  = lane & 3;

    // counters for my 4 segments: one 16B load
    uint4 c4 = *reinterpret_cast<const uint4*>(g_cnt + b * NREP + part * 4);
    int n[4] = {(int)c4.x, (int)c4.y, (int)c4.z, (int)c4.w};
    #pragma unroll
    for (int rr = 0; rr < 4; rr++) if (n[rr] > RCAP) n[rr] = RCAP;

    // all 4 bucket chunks in flight before any processing
    const unsigned* segbase = g_bucket + (size_t)b * CAPTOT + part * (4 * RCAP);
    unsigned pk[4];
    #pragma unroll
    for (int rr = 0; rr < 4; rr++)
        pk[rr] = (lane < n[rr]) ? __ldg(segbase + rr * RCAP + lane) : 0u;

    float acc[8] = {0.f, 0.f, 0.f, 0.f, 0.f, 0.f, 0.f, 0.f};
    if (part == 0 && oct == 0) {           // fold (normally zero) overflow row once
        float4 a0 = *reinterpret_cast<const float4*>(g_acc + (size_t)b * BC + sub * 8);
        float4 a1 = *reinterpret_cast<const float4*>(g_acc + (size_t)b * BC + sub * 8 + 4);
        acc[0] = a0.x; acc[1] = a0.y; acc[2] = a0.z; acc[3] = a0.w;
        acc[4] = a1.x; acc[5] = a1.y; acc[6] = a1.z; acc[7] = a1.w;
    }

    const char* xbase = reinterpret_cast<const char*>(g_xTh);

    #pragma unroll
    for (int rr = 0; rr < 4; rr++) {
        #pragma unroll
        for (int s = 0; s < RCAP; s += 8) {
            if (s >= n[rr]) break;         // warp-uniform, chunk granularity
            unsigned pv = __shfl_sync(0xffffffffu, pk[rr], s + oct);
            float w = __half2float(__ushort_as_half((unsigned short)(pv & 0xffffu)));
            unsigned off = (pv >> 10) & 0xFFFFC0u;   // pixel * 64 bytes
            uint4 u = __ldg(reinterpret_cast<const uint4*>(xbase + off + sub * 16));
            float2 f0 = __half22float2(*reinterpret_cast<__half2*>(&u.x));
            float2 f1 = __half22float2(*reinterpret_cast<__half2*>(&u.y));
            float2 f2 = __half22float2(*reinterpret_cast<__half2*>(&u.z));
            float2 f3 = __half22float2(*reinterpret_cast<__half2*>(&u.w));
            acc[0] += f0.x * w;  acc[1] += f0.y * w;
            acc[2] += f1.x * w;  acc[3] += f1.y * w;
            acc[4] += f2.x * w;  acc[5] += f2.y * w;
            acc[6] += f3.x * w;  acc[7] += f3.y * w;
        }
    }

    // fold the 8 oct groups (vote selectors): xor offsets 4, 8, 16
    #pragma unroll
    for (int ofs = 4; ofs <= 16; ofs <<= 1) {
        #pragma unroll
        for (int i = 0; i < 8; i++)
            acc[i] += __shfl_xor_sync(0xffffffffu, acc[i], ofs);
    }

    if (oct == 0) {                        // lanes 0..3 hold maps [8*sub, 8*sub+8)
        #pragma unroll
        for (int i = 0; i < 8; i++)
            s_part[bl][part][sub * 8 + i] = acc[i];
    }
    __syncthreads();

    int t = threadIdx.x;
    if (t < 128) {
        // t = m*4 + bl -> 4 consecutive bins per map (16B coalesced)
        int m   = t >> 2;
        int obl = t & 3;
        float v = s_part[obl][0][m] + s_part[obl][1][m];
        out[(size_t)m * HT_BINS + b0 + obl] = v * INV_NORM;
    }
    // re-zero state for the next call (all reads of g_cnt/g_acc happened
    // before the __syncthreads above)
    if (t < 8)                             // 4 bins * 8 counters = 32 ints = 8 int4
        reinterpret_cast<int4*>(g_cnt + b0 * NREP)[t] = make_int4(0, 0, 0, 0);
    if (t >= 128 && t < 160)               // 4 bins * 32 floats = 128 floats = 32 float4
        reinterpret_cast<float4*>(g_acc + (size_t)b0 * BC)[t - 128] =
            make_float4(0.f, 0.f, 0.f, 0.f);
}

// ---------------------------------------------------------------------------
// Launch pipeline: 2 kernels, all async, graph-capturable
// ---------------------------------------------------------------------------
extern "C" void kernel_launch(void* const* d_in, const int* in_sizes, int n_in,
                              void* d_out, int out_size) {
    const float* x  = (const float*)d_in[0];   // [2,16,128,128] fp32
    const int*   vp = (const int*)  d_in[1];   // vote_pixel  [4M]
    const int*   vb = (const int*)  d_in[2];   // vote_bin    [4M]
    const float* vw = (const float*)d_in[3];   // vote_weight [4M]
    float* out = (float*)d_out;                // [2,16,184,180] fp32

    scatter_transpose_kernel<<<TRANS_BLOCKS + SCAT_BLOCKS, 256>>>(x, vp, vb, vw);
    accum_kernel            <<<HT_BINS / 4, 256>>>(out);
}